// round 10
// baseline (speedup 1.0000x reference)
#include <cuda_runtime.h>
#include <cuda_bf16.h>
#include <math.h>

#define NN 5000
#define NL 20000
#define NP 50000

typedef unsigned long long ull;

// ------------------------- device-global scratch -------------------------
__device__ __align__(16) float g_link[2][NL * 32];
__device__ __align__(16) float g_node[2][NN * 32];
__device__ __align__(16) float g_path[NP * 64];
__device__ __align__(16) float g_m[NL * 64];
__device__ __align__(16) float g_Lx[NL * 192];
__device__ __align__(16) float g_Nx[NN * 192];
__device__ __align__(16) float g_z[(size_t)NN * 1056];
__device__ __align__(16) float g_W2[32768];
__device__ __align__(16) float g_We[4096];
__device__ __align__(16) float g_be[32];
// B fragments for mma.sync m16n8k16: [gate][hi/lo][kt][nt][lane] = {b0,b1}
__device__ __align__(16) uint2 g_Bfrag[3][2][4][8][32];

// ------------------------------ helpers ----------------------------------
__device__ __forceinline__ float sigm(float x) {
    return __fdividef(1.0f, 1.0f + __expf(-x));
}
__device__ __forceinline__ float tanh_fast(float x) {
    float ax = fabsf(x);
    float e  = __expf(-2.0f * ax);
    float t  = __fdividef(1.0f - e, 1.0f + e);
    return copysignf(t, x);
}
__device__ __forceinline__ float selu_f(float x) {
    return x > 0.0f ? 1.0507009873554805f * x
                    : 1.7580993408473766f * (__expf(x) - 1.0f);
}
__device__ __forceinline__ void red4(float* a, float x, float y, float z, float w) {
    asm volatile("red.global.add.v4.f32 [%0], {%1,%2,%3,%4};"
                 :: "l"(a), "f"(x), "f"(y), "f"(z), "f"(w) : "memory");
}
__device__ __forceinline__ void red2(float* a, float x, float y) {
    asm volatile("red.global.add.v2.f32 [%0], {%1,%2};"
                 :: "l"(a), "f"(x), "f"(y) : "memory");
}
__device__ __forceinline__ ull pack2(float a, float b) {
    ull r; asm("mov.b64 %0, {%1,%2};" : "=l"(r) : "f"(a), "f"(b)); return r;
}
__device__ __forceinline__ void ffma2(ull& acc, ull a, ull b) {
    asm("fma.rn.f32x2 %0, %1, %2, %0;" : "+l"(acc) : "l"(a), "l"(b));
}
__device__ __forceinline__ void unpack2(ull v, float& lo, float& hi) {
    asm("mov.b64 {%0,%1}, %2;" : "=f"(lo), "=f"(hi) : "l"(v));
}
__device__ __forceinline__ unsigned bfp(float x, float y) {
    return (unsigned)__bfloat16_as_ushort(__float2bfloat16(x))
         | ((unsigned)__bfloat16_as_ushort(__float2bfloat16(y)) << 16);
}
__device__ __forceinline__ float bf_lo(unsigned u) {
    return __bfloat162float(__ushort_as_bfloat16((unsigned short)(u & 0xFFFF)));
}
__device__ __forceinline__ float bf_hi(unsigned u) {
    return __bfloat162float(__ushort_as_bfloat16((unsigned short)(u >> 16)));
}

#define MMA16816(d, a0, a1, a2, a3, b0, b1)                                 \
    asm volatile(                                                           \
        "mma.sync.aligned.m16n8k16.row.col.f32.bf16.bf16.f32 "              \
        "{%0,%1,%2,%3}, {%4,%5,%6,%7}, {%8,%9}, {%0,%1,%2,%3};"             \
        : "+f"((d)[0]), "+f"((d)[1]), "+f"((d)[2]), "+f"((d)[3])            \
        : "r"(a0), "r"(a1), "r"(a2), "r"(a3), "r"(b0), "r"(b1))

// ----------------------------- prep kernels ------------------------------
// B frag: gate g covers wh cols [g*64, g*64+64); lane layout per PTX m16n8k16
__global__ void prep_bfrag_k(const float* __restrict__ wh) {
    int idx = blockIdx.x * 256 + threadIdx.x;   // 6144
    if (idx >= 6144) return;
    int lane = idx & 31;
    int nt   = (idx >> 5) & 7;
    int kt   = (idx >> 8) & 3;
    int mat  = (idx >> 10) & 1;
    int gate = idx >> 11;
    int n = gate * 64 + nt * 8 + (lane >> 2);
    int k = kt * 16 + (lane & 3) * 2;
    unsigned short v[4];
    #pragma unroll
    for (int q = 0; q < 4; q++) {
        int kk = k + (q & 1) + (q >> 1) * 8;
        float w = wh[kk * 192 + n];
        __nv_bfloat16 hi = __float2bfloat16(w);
        v[q] = (mat == 0) ? __bfloat16_as_ushort(hi)
                          : __bfloat16_as_ushort(__float2bfloat16(w - __bfloat162float(hi)));
    }
    g_Bfrag[gate][mat][kt][nt][lane] =
        make_uint2((unsigned)v[0] | ((unsigned)v[1] << 16),
                   (unsigned)v[2] | ((unsigned)v[3] << 16));
}

__global__ void prep_edge_k(const float* __restrict__ w1, const float* __restrict__ b1,
                            const float* __restrict__ w2, const float* __restrict__ b2) {
    int idx = blockIdx.x * 256 + threadIdx.x;
    if (idx < 4096) {
        int c = idx >> 5, j = idx & 31;
        float acc = 0.0f;
        #pragma unroll
        for (int k = 0; k < 32; k++) acc += w1[c * 32 + k] * w2[k * 32 + j];
        g_We[idx] = acc;
    } else if (idx < 4096 + 32) {
        int j = idx - 4096;
        float acc = b2[j];
        #pragma unroll
        for (int k = 0; k < 32; k++) acc += b1[k] * w2[k * 32 + j];
        g_be[j] = acc;
    }
}

__global__ void prep_w2_k(const float* __restrict__ wk) {
    int idx = blockIdx.x * 256 + threadIdx.x;
    int o = idx & 31;
    int i = (idx >> 5) & 31;
    int c = idx >> 10;
    g_W2[i * 1024 + c * 32 + o] = wk[idx];
}

__global__ void init_all_k(const float* __restrict__ li,
                           const float* __restrict__ ni,
                           const float* __restrict__ pi) {
    int idx = blockIdx.x * 256 + threadIdx.x;
    if (idx < NL * 32) {
        int l = idx >> 5, c = idx & 31;
        g_link[0][idx] = (c == 0) ? li[l] : 0.0f;
    } else if (idx < NL * 32 + NN * 32) {
        int r = idx - NL * 32;
        int n = r >> 5, c = r & 31;
        g_node[0][r] = (c == 0) ? ni[n] : 0.0f;
    } else if (idx < NL * 32 + NN * 32 + NP * 64) {
        int r = idx - NL * 32 - NN * 32;
        int p = r >> 6, c = r & 63;
        float v = 0.0f;
        if (c == 0) v = pi[p];
        else if (c == 1) v = pi[NP + p];
        g_path[r] = v;
    }
}

__global__ void zero_m_k() {
    int idx = blockIdx.x * 256 + threadIdx.x;
    ((float4*)g_m)[idx] = make_float4(0.f, 0.f, 0.f, 0.f);
}

// ---------- merged Lx/Nx. Links get b0[j] + (j<128 ? b1[j] : 0) folded ----
__global__ void __launch_bounds__(192) lxnx_kernel(const float* __restrict__ wx,
                                                   const float* __restrict__ b, int cur) {
    __shared__ float swx[6144];
    __shared__ float sst[8][33];
    int tid = threadIdx.x;
    bool is_link = (blockIdx.x < 2500);
    const float* wsrc = is_link ? wx : wx + 6144;
    for (int r = tid; r < 6144; r += 192) swx[r] = wsrc[r];
    const float* st = is_link ? g_link[cur] : g_node[cur];
    int base = is_link ? blockIdx.x * 8 : (blockIdx.x - 2500) * 8;
    for (int r = tid; r < 256; r += 192) {
        int e = r >> 5, c = r & 31;
        sst[e][c] = st[(size_t)(base + e) * 32 + c];
    }
    __syncthreads();
    int j = tid;
    float bj = 0.0f;
    if (is_link) bj = b[j] + (j < 128 ? b[192 + j] : 0.0f);
    float* dst = is_link ? g_Lx : g_Nx;
    for (int e = 0; e < 8; e++) {
        float acc = bj;
        #pragma unroll
        for (int i = 0; i < 32; i++) acc += sst[e][i] * swx[i * 192 + j];
        dst[(size_t)(base + e) * 192 + j] = acc;
    }
}

// --------------------- HMMA GRU scan: 128 paths/CTA -----------------------
// smem bytes: sgx f32[128][68] 34816 | saHi bf16[128][68] 17408 |
//             saLo 17408 | sli 512 | sni 512 | sb1h 256  = 70912
#define GRU_SMEM_BYTES 70912

template <int SCATTER>
__global__ void __launch_bounds__(128, 2) gru_kernel(const int* __restrict__ l2p,
                                                     const int* __restrict__ n2p,
                                                     const float* __restrict__ gb) {
    extern __shared__ float sm[];
    float* sgx = sm;                                        // [128][68]
    unsigned short* saHi = (unsigned short*)(sm + 8704);    // [128][68]
    unsigned short* saLo = saHi + 8704;
    int* sli = (int*)((char*)sm + 69632);
    int* sni = sli + 128;
    float* sb1h = (float*)(sni + 128);

    int tid = threadIdx.x;
    int lane = tid & 31, wid = tid >> 5;
    int g = lane >> 2, tg = lane & 3;
    int wbase = wid * 32;
    int pbase = blockIdx.x * 128;
    int pglob = pbase + tid;
    bool valid = (pglob < NP);
    int pc = valid ? pglob : NP - 1;

    if (tid < 64) sb1h[tid] = gb[320 + tid];

    // initial h -> bf16 hi/lo staging (row tid)
    {
        const float4* gp = (const float4*)g_path + (size_t)pc * 16;
        #pragma unroll
        for (int q = 0; q < 16; q++) {
            float4 v = gp[q];
            __nv_bfloat16 hx = __float2bfloat16(v.x), hy = __float2bfloat16(v.y);
            __nv_bfloat16 hz = __float2bfloat16(v.z), hw = __float2bfloat16(v.w);
            *(unsigned*)(saHi + tid * 68 + 4 * q) =
                (unsigned)__bfloat16_as_ushort(hx) | ((unsigned)__bfloat16_as_ushort(hy) << 16);
            *(unsigned*)(saHi + tid * 68 + 4 * q + 2) =
                (unsigned)__bfloat16_as_ushort(hz) | ((unsigned)__bfloat16_as_ushort(hw) << 16);
            *(unsigned*)(saLo + tid * 68 + 4 * q) =
                bfp(v.x - __bfloat162float(hx), v.y - __bfloat162float(hy));
            *(unsigned*)(saLo + tid * 68 + 4 * q + 2) =
                bfp(v.z - __bfloat162float(hz), v.w - __bfloat162float(hw));
        }
    }

    const float4* Lx4 = (const float4*)g_Lx;
    const float4* Nx4 = (const float4*)g_Nx;

    for (int t = 0; t < 8; t++) {
        sli[tid] = l2p[pc * 8 + t];
        sni[tid] = n2p[pc * 8 + t];
        __syncthreads();

        float rc[64];

        #pragma unroll
        for (int phase = 0; phase < 3; phase++) {
            const int gate = (phase == 0) ? 1 : (phase == 1) ? 2 : 0;
            const int goff = gate * 16;   // float4 quads into the 192-wide row

            // ---- cooperative gather of this gate's gx slice ----
            #pragma unroll
            for (int r8 = 0; r8 < 16; r8++) {
                int idx = r8 * 128 + tid;
                int p = idx >> 4, q = idx & 15;
                float4 a = Lx4[(size_t)sli[p] * 48 + goff + q];
                float4 b = Nx4[(size_t)sni[p] * 48 + goff + q];
                *(float4*)(sgx + p * 68 + q * 4) =
                    make_float4(a.x + b.x, a.y + b.y, a.z + b.z, a.w + b.w);
            }
            __syncthreads();

            // ---- mma: D[2 m][8 nt][4] ----
            float D[2][8][4];
            #pragma unroll
            for (int m = 0; m < 2; m++)
                #pragma unroll
                for (int nt = 0; nt < 8; nt++)
                    #pragma unroll
                    for (int q = 0; q < 4; q++) D[m][nt][q] = 0.0f;

            #pragma unroll
            for (int kt = 0; kt < 4; kt++) {
                int k0 = kt * 16 + 2 * tg;
                unsigned ah[2][4], al[2][4];
                #pragma unroll
                for (int m = 0; m < 2; m++) {
                    int r0 = wbase + m * 16 + g;
                    ah[m][0] = *(unsigned*)(saHi + r0 * 68 + k0);
                    ah[m][1] = *(unsigned*)(saHi + (r0 + 8) * 68 + k0);
                    ah[m][2] = *(unsigned*)(saHi + r0 * 68 + k0 + 8);
                    ah[m][3] = *(unsigned*)(saHi + (r0 + 8) * 68 + k0 + 8);
                    al[m][0] = *(unsigned*)(saLo + r0 * 68 + k0);
                    al[m][1] = *(unsigned*)(saLo + (r0 + 8) * 68 + k0);
                    al[m][2] = *(unsigned*)(saLo + r0 * 68 + k0 + 8);
                    al[m][3] = *(unsigned*)(saLo + (r0 + 8) * 68 + k0 + 8);
                }
                #pragma unroll
                for (int nt = 0; nt < 8; nt++) {
                    uint2 bh = g_Bfrag[gate][0][kt][nt][lane];
                    uint2 bl = g_Bfrag[gate][1][kt][nt][lane];
                    MMA16816(D[0][nt], ah[0][0], ah[0][1], ah[0][2], ah[0][3], bh.x, bh.y);
                    MMA16816(D[0][nt], al[0][0], al[0][1], al[0][2], al[0][3], bh.x, bh.y);
                    MMA16816(D[0][nt], ah[0][0], ah[0][1], ah[0][2], ah[0][3], bl.x, bl.y);
                    MMA16816(D[1][nt], ah[1][0], ah[1][1], ah[1][2], ah[1][3], bh.x, bh.y);
                    MMA16816(D[1][nt], al[1][0], al[1][1], al[1][2], al[1][3], bh.x, bh.y);
                    MMA16816(D[1][nt], ah[1][0], ah[1][1], ah[1][2], ah[1][3], bl.x, bl.y);
                }
            }

            // ---- epilogue ----
            #pragma unroll
            for (int m = 0; m < 2; m++) {
                int p0 = wbase + m * 16 + g;
                int p1 = p0 + 8;
                #pragma unroll
                for (int nt = 0; nt < 8; nt++) {
                    int jl = nt * 8 + 2 * tg;
                    int ri = m * 32 + nt * 4;
                    float2 gx0 = *(float2*)(sgx + p0 * 68 + jl);
                    float2 gx1 = *(float2*)(sgx + p1 * 68 + jl);
                    if (phase == 0) {            // gate r
                        rc[ri + 0] = sigm(gx0.x + D[m][nt][0]);
                        rc[ri + 1] = sigm(gx0.y + D[m][nt][1]);
                        rc[ri + 2] = sigm(gx1.x + D[m][nt][2]);
                        rc[ri + 3] = sigm(gx1.y + D[m][nt][3]);
                    } else if (phase == 1) {     // gate c
                        float2 bb = *(float2*)(sb1h + jl);
                        rc[ri + 0] = tanh_fast(gx0.x + rc[ri + 0] * (D[m][nt][0] + bb.x));
                        rc[ri + 1] = tanh_fast(gx0.y + rc[ri + 1] * (D[m][nt][1] + bb.y));
                        rc[ri + 2] = tanh_fast(gx1.x + rc[ri + 2] * (D[m][nt][2] + bb.x));
                        rc[ri + 3] = tanh_fast(gx1.y + rc[ri + 3] * (D[m][nt][3] + bb.y));
                    } else {                     // gate z + combine
                        float z0 = sigm(gx0.x + D[m][nt][0]);
                        float z1 = sigm(gx0.y + D[m][nt][1]);
                        float z2 = sigm(gx1.x + D[m][nt][2]);
                        float z3 = sigm(gx1.y + D[m][nt][3]);
                        unsigned uh0 = *(unsigned*)(saHi + p0 * 68 + jl);
                        unsigned ul0 = *(unsigned*)(saLo + p0 * 68 + jl);
                        unsigned uh1 = *(unsigned*)(saHi + p1 * 68 + jl);
                        unsigned ul1 = *(unsigned*)(saLo + p1 * 68 + jl);
                        float h00 = bf_lo(uh0) + bf_lo(ul0);
                        float h01 = bf_hi(uh0) + bf_hi(ul0);
                        float h10 = bf_lo(uh1) + bf_lo(ul1);
                        float h11 = bf_hi(uh1) + bf_hi(ul1);
                        float n00 = z0 * h00 + (1.0f - z0) * rc[ri + 0];
                        float n01 = z1 * h01 + (1.0f - z1) * rc[ri + 1];
                        float n10 = z2 * h10 + (1.0f - z2) * rc[ri + 2];
                        float n11 = z3 * h11 + (1.0f - z3) * rc[ri + 3];
                        __nv_bfloat16 b00 = __float2bfloat16(n00), b01 = __float2bfloat16(n01);
                        __nv_bfloat16 b10 = __float2bfloat16(n10), b11 = __float2bfloat16(n11);
                        *(unsigned*)(saHi + p0 * 68 + jl) =
                            (unsigned)__bfloat16_as_ushort(b00) | ((unsigned)__bfloat16_as_ushort(b01) << 16);
                        *(unsigned*)(saLo + p0 * 68 + jl) =
                            bfp(n00 - __bfloat162float(b00), n01 - __bfloat162float(b01));
                        *(unsigned*)(saHi + p1 * 68 + jl) =
                            (unsigned)__bfloat16_as_ushort(b10) | ((unsigned)__bfloat16_as_ushort(b11) << 16);
                        *(unsigned*)(saLo + p1 * 68 + jl) =
                            bfp(n10 - __bfloat162float(b10), n11 - __bfloat162float(b11));
                        if (SCATTER) {
                            if (pbase + p0 < NP) red2(g_m + (size_t)sli[p0] * 64 + jl, n00, n01);
                            if (pbase + p1 < NP) red2(g_m + (size_t)sli[p1] * 64 + jl, n10, n11);
                        }
                    }
                }
            }
            __syncthreads();
        }
    }

    // final h writeback (row tid, reconstruct hi+lo)
    if (valid) {
        float4* gp = (float4*)g_path + (size_t)pglob * 16;
        #pragma unroll
        for (int q = 0; q < 16; q++) {
            unsigned uh0 = *(unsigned*)(saHi + tid * 68 + 4 * q);
            unsigned ul0 = *(unsigned*)(saLo + tid * 68 + 4 * q);
            unsigned uh1 = *(unsigned*)(saHi + tid * 68 + 4 * q + 2);
            unsigned ul1 = *(unsigned*)(saLo + tid * 68 + 4 * q + 2);
            gp[q] = make_float4(bf_lo(uh0) + bf_lo(ul0), bf_hi(uh0) + bf_hi(ul0),
                                bf_lo(uh1) + bf_lo(ul1), bf_hi(uh1) + bf_hi(ul1));
        }
    }
}

// ------- z[s][c*32+o] = sum_i node[s][i] * W2[i][c*32+o];  + beta cols ----
__global__ void __launch_bounds__(256) z_kernel(const float* __restrict__ bk, int cur) {
    __shared__ __align__(16) float Ns[512];
    int tid = threadIdx.x;
    int n0 = blockIdx.x * 16;
    const float* nst = g_node[cur];
    for (int r = tid; r < 512; r += 256) {
        int i = r >> 4, nl = r & 15;
        int nn = n0 + nl; if (nn >= NN) nn = NN - 1;
        Ns[r] = nst[(size_t)nn * 32 + i];
    }
    __syncthreads();
    int o = blockIdx.y * 512 + tid;
    ull acc0[8], acc1[8];
    #pragma unroll
    for (int q = 0; q < 8; q++) { acc0[q] = 0ull; acc1[q] = 0ull; }
    for (int i = 0; i < 32; i++) {
        float w0 = g_W2[i * 1024 + o];
        float w1 = g_W2[i * 1024 + o + 256];
        ull w0p = pack2(w0, w0);
        ull w1p = pack2(w1, w1);
        const ulonglong2* np = (const ulonglong2*)(Ns + i * 16);
        #pragma unroll
        for (int q2 = 0; q2 < 4; q2++) {
            ulonglong2 nv = np[q2];
            ffma2(acc0[q2 * 2 + 0], nv.x, w0p);
            ffma2(acc0[q2 * 2 + 1], nv.y, w0p);
            ffma2(acc1[q2 * 2 + 0], nv.x, w1p);
            ffma2(acc1[q2 * 2 + 1], nv.y, w1p);
        }
    }
    #pragma unroll
    for (int q = 0; q < 8; q++) {
        float v0, v1, u0, u1;
        unpack2(acc0[q], v0, v1);
        unpack2(acc1[q], u0, u1);
        int na = n0 + 2 * q, nb = n0 + 2 * q + 1;
        if (na < NN) { g_z[(size_t)na * 1056 + o] = v0; g_z[(size_t)na * 1056 + o + 256] = u0; }
        if (nb < NN) { g_z[(size_t)nb * 1056 + o] = v1; g_z[(size_t)nb * 1056 + o + 256] = u1; }
    }
    if (blockIdx.y == 0) {
        int nl = tid >> 5;
        int oo = tid & 31;
        float b0 = 0.0f, b1 = 0.0f;
        #pragma unroll
        for (int i = 0; i < 32; i++) {
            float bkv = bk[i * 32 + oo];
            b0 += Ns[i * 16 + nl] * bkv;
            b1 += Ns[i * 16 + nl + 8] * bkv;
        }
        if (n0 + nl < NN)     g_z[(size_t)(n0 + nl) * 1056 + 1024 + oo] = b0;
        if (n0 + nl + 8 < NN) g_z[(size_t)(n0 + nl + 8) * 1056 + 1024 + oo] = b1;
    }
}

// --------- root (stores): node1 = broot + node0@wroot ---------------------
__global__ void __launch_bounds__(256) root_kernel(const float* __restrict__ wroot,
                                                   const float* __restrict__ broot,
                                                   int cur, int nxt) {
    __shared__ float sw[1024];
    int tid = threadIdx.x;
    for (int i = tid; i < 1024; i += 256) sw[i] = wroot[i];
    __syncthreads();
    int w = tid >> 5, lane = tid & 31;
    int n = blockIdx.x * 8 + w;
    const float* nr = g_node[cur] + (size_t)n * 32;
    float acc = broot[lane];
    #pragma unroll
    for (int i = 0; i < 32; i++) acc += nr[i] * sw[i * 32 + lane];
    g_node[nxt][(size_t)n * 32 + lane] = acc;
}

// ----- fused edge MLP + ECC message --------------------------------------
__global__ void __launch_bounds__(256) edge_msg_kernel(const int* __restrict__ l2n,
                                                       const int* __restrict__ senders,
                                                       const int* __restrict__ recv,
                                                       int cur, int nxt) {
    __shared__ float sWe[4096];
    __shared__ float sbe[32];
    __shared__ float con[8][128];
    __shared__ float sL[8][32];
    int tid = threadIdx.x;
    for (int i = tid; i < 4096; i += 256) sWe[i] = g_We[i];
    if (tid < 32) sbe[tid] = g_be[tid];
    int w = tid >> 5, lane = tid & 31;
    int l = blockIdx.x * 8 + w;
    int nn = l2n[l];
    con[w][lane]      = g_node[cur][(size_t)nn * 32 + lane];
    con[w][32 + lane] = g_link[cur][(size_t)l * 32 + lane];
    con[w][64 + lane] = g_m[(size_t)l * 64 + lane];
    con[w][96 + lane] = g_m[(size_t)l * 64 + 32 + lane];
    __syncthreads();
    float acc = sbe[lane];
    #pragma unroll
    for (int c = 0; c < 128; c++) acc += con[w][c] * sWe[c * 32 + lane];
    g_link[nxt][(size_t)l * 32 + lane] = acc;
    sL[w][lane] = acc;
    __syncwarp();
    int s = senders[l];
    const float* zr = g_z + (size_t)s * 1056;
    float macc = zr[1024 + lane];
    #pragma unroll
    for (int c = 0; c < 32; c++) macc += sL[w][c] * zr[c * 32 + lane];
    atomicAdd(&g_node[nxt][(size_t)recv[l] * 32 + lane], macc);
}

// ---------------- readout -------------------------------------------------
__global__ void __launch_bounds__(256) readout_kernel(
    const float* __restrict__ rw1, const float* __restrict__ rb1,
    const float* __restrict__ rw2, const float* __restrict__ rb2,
    const float* __restrict__ fw,  const float* __restrict__ fb,
    float* __restrict__ out) {
    __shared__ float sw1[2048], sw2[1024], sfw[96];
    __shared__ float shp[8][64], sr1[8][33];
    int tid = threadIdx.x, w = tid >> 5, lane = tid & 31;
    for (int i = tid; i < 2048; i += 256) sw1[i] = rw1[i];
    for (int i = tid; i < 1024; i += 256) sw2[i] = rw2[i];
    if (tid < 96) sfw[tid] = fw[tid];
    int p = blockIdx.x * 8 + w;
    shp[w][lane]      = g_path[(size_t)p * 64 + lane];
    shp[w][32 + lane] = g_path[(size_t)p * 64 + 32 + lane];
    __syncthreads();
    float acc = rb1[lane];
    #pragma unroll
    for (int i = 0; i < 64; i++) acc += shp[w][i] * sw1[i * 32 + lane];
    float r1 = selu_f(acc);
    sr1[w][lane] = r1;
    __syncwarp();
    float acc2 = rb2[lane];
    #pragma unroll
    for (int i = 0; i < 32; i++) acc2 += sr1[w][i] * sw2[i * 32 + lane];
    float r2 = selu_f(acc2);
    float part = r2 * sfw[lane] + shp[w][lane] * sfw[32 + lane]
               + shp[w][32 + lane] * sfw[64 + lane];
    #pragma unroll
    for (int o = 16; o; o >>= 1) part += __shfl_down_sync(0xffffffffu, part, o);
    if (lane == 0) out[p] = part + fb[0];
}

// ---------------------------- launcher ------------------------------------
extern "C" void kernel_launch(void* const* d_in, const int* in_sizes, int n_in,
                              void* d_out, int out_size) {
    const float* link_init = (const float*)d_in[0];
    const float* node_init = (const float*)d_in[1];
    const float* path_init = (const float*)d_in[2];
    const float* gru_wx    = (const float*)d_in[3];
    const float* gru_wh    = (const float*)d_in[4];
    const float* gru_b     = (const float*)d_in[5];
    const float* e_w1      = (const float*)d_in[6];
    const float* e_b1      = (const float*)d_in[7];
    const float* e_w2      = (const float*)d_in[8];
    const float* e_b2      = (const float*)d_in[9];
    const float* ecc_wk    = (const float*)d_in[10];
    const float* ecc_bk    = (const float*)d_in[11];
    const float* ecc_wroot = (const float*)d_in[12];
    const float* ecc_broot = (const float*)d_in[13];
    const float* r_w1      = (const float*)d_in[14];
    const float* r_b1      = (const float*)d_in[15];
    const float* r_w2      = (const float*)d_in[16];
    const float* r_b2      = (const float*)d_in[17];
    const float* f_w       = (const float*)d_in[18];
    const float* f_b       = (const float*)d_in[19];
    const int* l2p   = (const int*)d_in[22];
    const int* n2p   = (const int*)d_in[23];
    const int* l2n   = (const int*)d_in[24];
    const int* senders   = (const int*)d_in[25];
    const int* receivers = (const int*)d_in[26];
    float* out = (float*)d_out;

    cudaFuncSetAttribute(gru_kernel<1>, cudaFuncAttributeMaxDynamicSharedMemorySize,
                         GRU_SMEM_BYTES);
    cudaFuncSetAttribute(gru_kernel<0>, cudaFuncAttributeMaxDynamicSharedMemorySize,
                         GRU_SMEM_BYTES);

    prep_bfrag_k<<<24, 256>>>(gru_wh);                                // 0
    init_all_k<<<15625, 256>>>(link_init, node_init, path_init);      // 1
    lxnx_kernel<<<3125, 192>>>(gru_wx, gru_b, 0);                     // 2
    zero_m_k<<<1250, 256>>>();                                        // 3
    prep_w2_k<<<128, 256>>>(ecc_wk);                                  // 4
    gru_kernel<1><<<391, 128, GRU_SMEM_BYTES>>>(l2p, n2p, gru_b);     // 5
    z_kernel<<<dim3(313, 2), 256>>>(ecc_bk, 0);                       // 6
    root_kernel<<<625, 256>>>(ecc_wroot, ecc_broot, 0, 1);            // 7
    prep_edge_k<<<17, 256>>>(e_w1, e_b1, e_w2, e_b2);                 // 8
    edge_msg_kernel<<<2500, 256>>>(l2n, senders, receivers, 0, 1);    // 9

    lxnx_kernel<<<3125, 192>>>(gru_wx, gru_b, 1);                     // 10
    gru_kernel<0><<<391, 128, GRU_SMEM_BYTES>>>(l2p, n2p, gru_b);     // 11

    readout_kernel<<<6250, 256>>>(r_w1, r_b1, r_w2, r_b2, f_w, f_b, out); // 12
}

// round 11
// speedup vs baseline: 1.3399x; 1.3399x over previous
#include <cuda_runtime.h>
#include <math.h>

#define NN 5000
#define NL 20000
#define NP 50000

typedef unsigned long long ull;

// ------------------------- device-global scratch -------------------------
__device__ __align__(16) float g_link[2][NL * 32];
__device__ __align__(16) float g_node[2][NN * 32];
__device__ __align__(16) float g_path[NP * 64];
__device__ __align__(16) float g_m[NL * 64];
__device__ __align__(16) float g_Lx[NL * 192];
__device__ __align__(16) float g_Nx[NN * 192];
__device__ __align__(16) float g_z[(size_t)NN * 1056];
__device__ __align__(16) float g_W2[32768];
__device__ __align__(16) float g_wpack[12288];
__device__ __align__(16) float g_b1pack[192];
__device__ __align__(16) float g_We[4096];
__device__ __align__(16) float g_be[32];

// ------------------------------ helpers ----------------------------------
__device__ __forceinline__ float sigm(float x) {
    return __fdividef(1.0f, 1.0f + __expf(-x));
}
__device__ __forceinline__ float tanh_fast(float x) {
    float ax = fabsf(x);
    float e  = __expf(-2.0f * ax);
    float t  = __fdividef(1.0f - e, 1.0f + e);
    return copysignf(t, x);
}
__device__ __forceinline__ float selu_f(float x) {
    return x > 0.0f ? 1.0507009873554805f * x
                    : 1.7580993408473766f * (__expf(x) - 1.0f);
}
__device__ __forceinline__ void red4(float* a, float x, float y, float z, float w) {
    asm volatile("red.global.add.v4.f32 [%0], {%1,%2,%3,%4};"
                 :: "l"(a), "f"(x), "f"(y), "f"(z), "f"(w) : "memory");
}
__device__ __forceinline__ ull pack2(float a, float b) {
    ull r; asm("mov.b64 %0, {%1,%2};" : "=l"(r) : "f"(a), "f"(b)); return r;
}
__device__ __forceinline__ void ffma2(ull& acc, ull a, ull b) {
    asm("fma.rn.f32x2 %0, %1, %2, %0;" : "+l"(acc) : "l"(a), "l"(b));
}
__device__ __forceinline__ void unpack2(ull v, float& lo, float& hi) {
    asm("mov.b64 {%0,%1}, %2;" : "=f"(lo), "=f"(hi) : "l"(v));
}

// ------------- merged prep: gru pack | fused edge MLP | W2 permute --------
__global__ void prep_all_k(const float* __restrict__ wh, const float* __restrict__ b,
                           const float* __restrict__ w1, const float* __restrict__ b1,
                           const float* __restrict__ w2, const float* __restrict__ b2,
                           const float* __restrict__ wk) {
    int idx = blockIdx.x * 256 + threadIdx.x;
    if (idx < 12288) {
        int k = idx & 3;
        int q = idx >> 2;
        int g = q % 3;
        int m2 = q / 3;
        int jg = m2 & 15;
        int i  = m2 >> 4;
        g_wpack[idx] = wh[i * 192 + g * 64 + jg * 4 + k];
    } else if (idx < 12480) {
        int r = idx - 12288;
        int k = r & 3;
        int g = (r >> 2) % 3;
        int jg = (r >> 2) / 3;
        g_b1pack[r] = b[192 + g * 64 + jg * 4 + k];
    } else if (idx < 12480 + 4096) {
        int r = idx - 12480;
        int c = r >> 5, j = r & 31;
        float acc = 0.0f;
        #pragma unroll
        for (int k = 0; k < 32; k++) acc += w1[c * 32 + k] * w2[k * 32 + j];
        g_We[r] = acc;
    } else if (idx < 12480 + 4128) {
        int j = idx - 12480 - 4096;
        float acc = b2[j];
        #pragma unroll
        for (int k = 0; k < 32; k++) acc += b1[k] * w2[k * 32 + j];
        g_be[j] = acc;
    } else if (idx < 12480 + 4128 + 32768) {
        int r = idx - 16608;
        int o = r & 31;
        int i = (r >> 5) & 31;
        int c = r >> 10;
        g_W2[i * 1024 + c * 32 + o] = wk[r];
    }
}

// -------------- merged init: link | node | path | zero m ------------------
__global__ void init_all_k(const float* __restrict__ li,
                           const float* __restrict__ ni,
                           const float* __restrict__ pi) {
    int idx = blockIdx.x * 256 + threadIdx.x;   // 5,280,000 total
    if (idx < NL * 32) {
        int l = idx >> 5, c = idx & 31;
        g_link[0][idx] = (c == 0) ? li[l] : 0.0f;
    } else if (idx < NL * 32 + NN * 32) {
        int r = idx - NL * 32;
        int n = r >> 5, c = r & 31;
        g_node[0][r] = (c == 0) ? ni[n] : 0.0f;
    } else if (idx < NL * 32 + NN * 32 + NP * 64) {
        int r = idx - NL * 32 - NN * 32;
        int p = r >> 6, c = r & 63;
        float v = 0.0f;
        if (c == 0) v = pi[p];
        else if (c == 1) v = pi[NP + p];
        g_path[r] = v;
    } else {
        g_m[idx - 4000000] = 0.0f;
    }
}

// ------ iter-1 Lx/Nx fast path (states are rank-1: only col 0 nonzero) ----
__global__ void __launch_bounds__(192) lxnx1_kernel(const float* __restrict__ wx,
                                                    const float* __restrict__ b,
                                                    const float* __restrict__ li,
                                                    const float* __restrict__ ni) {
    int tid = threadIdx.x;
    bool is_link = (blockIdx.x < 2500);
    int base = is_link ? blockIdx.x * 8 : (blockIdx.x - 2500) * 8;
    float wj = is_link ? wx[tid] : wx[6144 + tid];
    float bj = is_link ? b[tid] : 0.0f;
    const float* init = is_link ? li : ni;
    float* dst = is_link ? g_Lx : g_Nx;
    #pragma unroll
    for (int e = 0; e < 8; e++) {
        float v = init[base + e];
        dst[(size_t)(base + e) * 192 + tid] = v * wj + bj;
    }
}

// ---------- full Lx/Nx (iter 2): blocks [0,2500) links, rest nodes --------
__global__ void __launch_bounds__(192) lxnx_kernel(const float* __restrict__ wx,
                                                   const float* __restrict__ b, int cur) {
    __shared__ float swx[6144];
    __shared__ float sst[8][33];
    int tid = threadIdx.x;
    bool is_link = (blockIdx.x < 2500);
    const float* wsrc = is_link ? wx : wx + 6144;
    for (int r = tid; r < 6144; r += 192) swx[r] = wsrc[r];
    const float* st = is_link ? g_link[cur] : g_node[cur];
    int base = is_link ? blockIdx.x * 8 : (blockIdx.x - 2500) * 8;
    for (int r = tid; r < 256; r += 192) {
        int e = r >> 5, c = r & 31;
        sst[e][c] = st[(size_t)(base + e) * 32 + c];
    }
    __syncthreads();
    int j = tid;
    float bj = is_link ? b[j] : 0.0f;
    float* dst = is_link ? g_Lx : g_Nx;
    for (int e = 0; e < 8; e++) {
        float acc = bj;
        #pragma unroll
        for (int i = 0; i < 32; i++) acc += sst[e][i] * swx[i * 192 + j];
        dst[(size_t)(base + e) * 192 + j] = acc;
    }
}

// --------------------------- fused GRU scan ------------------------------
#define GRU_SMEM_BYTES 84736

#define GRU_I_BODY(i)                                                        \
    {                                                                        \
        float4 h4 = *(const float4*)(shH + (i) * 68 + pg * 4);               \
        ulonglong2 wz = w2m[((i) * 16 + jg) * 3 + 0];                        \
        ulonglong2 wr = w2m[((i) * 16 + jg) * 3 + 1];                        \
        ulonglong2 wh = w2m[((i) * 16 + jg) * 3 + 2];                        \
        ull hp0 = pack2(h4.x, h4.x);                                         \
        ull hp1 = pack2(h4.y, h4.y);                                         \
        ull hp2 = pack2(h4.z, h4.z);                                         \
        ull hp3 = pack2(h4.w, h4.w);                                         \
        ffma2(a2[0][0], hp0, wz.x); ffma2(a2[0][1], hp0, wz.y);              \
        ffma2(a2[0][2], hp0, wr.x); ffma2(a2[0][3], hp0, wr.y);              \
        ffma2(a2[0][4], hp0, wh.x); ffma2(a2[0][5], hp0, wh.y);              \
        ffma2(a2[1][0], hp1, wz.x); ffma2(a2[1][1], hp1, wz.y);              \
        ffma2(a2[1][2], hp1, wr.x); ffma2(a2[1][3], hp1, wr.y);              \
        ffma2(a2[1][4], hp1, wh.x); ffma2(a2[1][5], hp1, wh.y);              \
        ffma2(a2[2][0], hp2, wz.x); ffma2(a2[2][1], hp2, wz.y);              \
        ffma2(a2[2][2], hp2, wr.x); ffma2(a2[2][3], hp2, wr.y);              \
        ffma2(a2[2][4], hp2, wh.x); ffma2(a2[2][5], hp2, wh.y);              \
        ffma2(a2[3][0], hp3, wz.x); ffma2(a2[3][1], hp3, wz.y);              \
        ffma2(a2[3][2], hp3, wr.x); ffma2(a2[3][3], hp3, wr.y);              \
        ffma2(a2[3][4], hp3, wh.x); ffma2(a2[3][5], hp3, wh.y);              \
    }

template <int SCATTER, int FIRST>
__global__ void __launch_bounds__(256, 2) gru_kernel(const int* __restrict__ l2p,
                                                     const int* __restrict__ n2p) {
    extern __shared__ float sm[];
    float4* wsm = (float4*)sm;               // 3072 quads
    float*  sb1 = sm + 12288;                // 192
    float*  shh = sm + 12480;                // 2 * 4352

    int tid = threadIdx.x;
    int pg = tid >> 4, jg = tid & 15;
    int pbase = blockIdx.x * 64;

    const float4* wgl = (const float4*)g_wpack;
    #pragma unroll
    for (int r = 0; r < 12; r++) wsm[r * 256 + tid] = wgl[r * 256 + tid];
    if (tid < 192) sb1[tid] = g_b1pack[tid];

    const float4* gp4 = (const float4*)g_path;
    #pragma unroll
    for (int r = 0; r < 4; r++) {
        int idx = r * 256 + tid;
        int p = idx >> 4, iq = idx & 15;
        int pglob = pbase + p; if (pglob >= NP) pglob = NP - 1;
        float4 v = gp4[(size_t)pglob * 16 + iq];
        shh[(iq * 4 + 0) * 68 + p] = v.x;
        shh[(iq * 4 + 1) * 68 + p] = v.y;
        shh[(iq * 4 + 2) * 68 + p] = v.z;
        shh[(iq * 4 + 3) * 68 + p] = v.w;
    }
    __syncthreads();

    const ulonglong2* sb2 = (const ulonglong2*)sb1;
    ulonglong2 bA = sb2[jg * 3 + 0];
    ulonglong2 bB = sb2[jg * 3 + 1];
    ulonglong2 bC = sb2[jg * 3 + 2];

    int pid[4]; bool pv[4];
    #pragma unroll
    for (int pp = 0; pp < 4; pp++) {
        int pglob = pbase + pg * 4 + pp;
        pv[pp] = (pglob < NP);
        pid[pp] = pv[pp] ? pglob : NP - 1;
    }

    const float4* Lx4 = (const float4*)g_Lx;
    const float4* Nx4 = (const float4*)g_Nx;
    const ulonglong2* w2m = (const ulonglong2*)wsm;

    int hbuf = 0;
    for (int t = 0; t < 8; t++) {
        float4 gz[4], gr[4], gc[4];
        int liA[4];
        #pragma unroll
        for (int pp = 0; pp < 4; pp++) {
            int e = pid[pp] * 8 + t;
            int li = l2p[e], ni = n2p[e];
            liA[pp] = li;
            const float4* lq = Lx4 + (size_t)li * 48 + jg;
            const float4* nq = Nx4 + (size_t)ni * 48 + jg;
            float4 a0 = lq[0],  b0 = nq[0];
            float4 a1 = lq[16], b1 = nq[16];
            float4 a2q = lq[32], b2q = nq[32];
            gz[pp] = make_float4(a0.x + b0.x, a0.y + b0.y, a0.z + b0.z, a0.w + b0.w);
            gr[pp] = make_float4(a1.x + b1.x, a1.y + b1.y, a1.z + b1.z, a1.w + b1.w);
            gc[pp] = make_float4(a2q.x + b2q.x, a2q.y + b2q.y, a2q.z + b2q.z, a2q.w + b2q.w);
        }

        float* shH  = shh + hbuf * 4352;
        float* shHn = shh + (hbuf ^ 1) * 4352;

        ull a2[4][6];
        #pragma unroll
        for (int pp = 0; pp < 4; pp++) {
            a2[pp][0] = bA.x; a2[pp][1] = bA.y;
            a2[pp][2] = bB.x; a2[pp][3] = bB.y;
            a2[pp][4] = bC.x; a2[pp][5] = bC.y;
        }

        if (FIRST && t == 0) {
            // h0 has only hidden dims 0,1 nonzero — 2-term inner loop (bit-exact)
            GRU_I_BODY(0);
            GRU_I_BODY(1);
        } else {
            #pragma unroll 8
            for (int i = 0; i < 64; i++) GRU_I_BODY(i);
        }

        int j0 = jg * 4;
        #pragma unroll
        for (int pp = 0; pp < 4; pp++) {
            int p = pg * 4 + pp;
            float az0, az1, az2, az3, ar0, ar1, ar2, ar3, ah0, ah1, ah2, ah3;
            unpack2(a2[pp][0], az0, az1); unpack2(a2[pp][1], az2, az3);
            unpack2(a2[pp][2], ar0, ar1); unpack2(a2[pp][3], ar2, ar3);
            unpack2(a2[pp][4], ah0, ah1); unpack2(a2[pp][5], ah2, ah3);
            float z0 = sigm(gz[pp].x + az0);
            float z1 = sigm(gz[pp].y + az1);
            float z2 = sigm(gz[pp].z + az2);
            float z3 = sigm(gz[pp].w + az3);
            float r0 = sigm(gr[pp].x + ar0);
            float r1 = sigm(gr[pp].y + ar1);
            float r2 = sigm(gr[pp].z + ar2);
            float r3 = sigm(gr[pp].w + ar3);
            float c0 = tanh_fast(gc[pp].x + r0 * ah0);
            float c1 = tanh_fast(gc[pp].y + r1 * ah1);
            float c2 = tanh_fast(gc[pp].z + r2 * ah2);
            float c3 = tanh_fast(gc[pp].w + r3 * ah3);
            float h0 = shH[(j0 + 0) * 68 + p];
            float h1 = shH[(j0 + 1) * 68 + p];
            float h2 = shH[(j0 + 2) * 68 + p];
            float h3 = shH[(j0 + 3) * 68 + p];
            float n0 = z0 * h0 + (1.0f - z0) * c0;
            float n1 = z1 * h1 + (1.0f - z1) * c1;
            float n2 = z2 * h2 + (1.0f - z2) * c2;
            float n3 = z3 * h3 + (1.0f - z3) * c3;
            shHn[(j0 + 0) * 68 + p] = n0;
            shHn[(j0 + 1) * 68 + p] = n1;
            shHn[(j0 + 2) * 68 + p] = n2;
            shHn[(j0 + 3) * 68 + p] = n3;
            if (SCATTER && pv[pp]) {
                red4(g_m + (size_t)liA[pp] * 64 + j0, n0, n1, n2, n3);
            }
        }
        hbuf ^= 1;
        __syncthreads();
    }

    float* shF = shh + hbuf * 4352;
    #pragma unroll
    for (int r = 0; r < 4; r++) {
        int idx = r * 256 + tid;
        int p = idx >> 4, iq = idx & 15;
        int pglob = pbase + p;
        if (pglob < NP) {
            float4 v;
            v.x = shF[(iq * 4 + 0) * 68 + p];
            v.y = shF[(iq * 4 + 1) * 68 + p];
            v.z = shF[(iq * 4 + 2) * 68 + p];
            v.w = shF[(iq * 4 + 3) * 68 + p];
            ((float4*)g_path)[(size_t)pglob * 16 + iq] = v;
        }
    }
}

// ------- z[s][c*32+o] = sum_i node[s][i] * W2[i][c*32+o];  + beta cols ----
__global__ void __launch_bounds__(256) z_kernel(const float* __restrict__ bk, int cur) {
    __shared__ __align__(16) float Ns[512];
    int tid = threadIdx.x;
    int n0 = blockIdx.x * 16;
    const float* nst = g_node[cur];
    for (int r = tid; r < 512; r += 256) {
        int i = r >> 4, nl = r & 15;
        int nn = n0 + nl; if (nn >= NN) nn = NN - 1;
        Ns[r] = nst[(size_t)nn * 32 + i];
    }
    __syncthreads();
    int o = blockIdx.y * 512 + tid;
    ull acc0[8], acc1[8];
    #pragma unroll
    for (int q = 0; q < 8; q++) { acc0[q] = 0ull; acc1[q] = 0ull; }
    for (int i = 0; i < 32; i++) {
        float w0 = g_W2[i * 1024 + o];
        float w1 = g_W2[i * 1024 + o + 256];
        ull w0p = pack2(w0, w0);
        ull w1p = pack2(w1, w1);
        const ulonglong2* np = (const ulonglong2*)(Ns + i * 16);
        #pragma unroll
        for (int q2 = 0; q2 < 4; q2++) {
            ulonglong2 nv = np[q2];
            ffma2(acc0[q2 * 2 + 0], nv.x, w0p);
            ffma2(acc0[q2 * 2 + 1], nv.y, w0p);
            ffma2(acc1[q2 * 2 + 0], nv.x, w1p);
            ffma2(acc1[q2 * 2 + 1], nv.y, w1p);
        }
    }
    #pragma unroll
    for (int q = 0; q < 8; q++) {
        float v0, v1, u0, u1;
        unpack2(acc0[q], v0, v1);
        unpack2(acc1[q], u0, u1);
        int na = n0 + 2 * q, nb = n0 + 2 * q + 1;
        if (na < NN) { g_z[(size_t)na * 1056 + o] = v0; g_z[(size_t)na * 1056 + o + 256] = u0; }
        if (nb < NN) { g_z[(size_t)nb * 1056 + o] = v1; g_z[(size_t)nb * 1056 + o + 256] = u1; }
    }
    if (blockIdx.y == 0) {
        int nl = tid >> 5;
        int oo = tid & 31;
        float b0 = 0.0f, b1 = 0.0f;
        #pragma unroll
        for (int i = 0; i < 32; i++) {
            float bkv = bk[i * 32 + oo];
            b0 += Ns[i * 16 + nl] * bkv;
            b1 += Ns[i * 16 + nl + 8] * bkv;
        }
        if (n0 + nl < NN)     g_z[(size_t)(n0 + nl) * 1056 + 1024 + oo] = b0;
        if (n0 + nl + 8 < NN) g_z[(size_t)(n0 + nl + 8) * 1056 + 1024 + oo] = b1;
    }
}

// --------- root (stores): node1 = broot + node0@wroot ---------------------
__global__ void __launch_bounds__(256) root_kernel(const float* __restrict__ wroot,
                                                   const float* __restrict__ broot,
                                                   int cur, int nxt) {
    __shared__ float sw[1024];
    int tid = threadIdx.x;
    for (int i = tid; i < 1024; i += 256) sw[i] = wroot[i];
    __syncthreads();
    int w = tid >> 5, lane = tid & 31;
    int n = blockIdx.x * 8 + w;
    const float* nr = g_node[cur] + (size_t)n * 32;
    float acc = broot[lane];
    #pragma unroll
    for (int i = 0; i < 32; i++) acc += nr[i] * sw[i * 32 + lane];
    g_node[nxt][(size_t)n * 32 + lane] = acc;
}

// ----- fused edge MLP + ECC message --------------------------------------
__global__ void __launch_bounds__(256) edge_msg_kernel(const int* __restrict__ l2n,
                                                       const int* __restrict__ senders,
                                                       const int* __restrict__ recv,
                                                       int cur, int nxt) {
    __shared__ float sWe[4096];
    __shared__ float sbe[32];
    __shared__ float con[8][128];
    __shared__ float sL[8][32];
    int tid = threadIdx.x;
    for (int i = tid; i < 4096; i += 256) sWe[i] = g_We[i];
    if (tid < 32) sbe[tid] = g_be[tid];
    int w = tid >> 5, lane = tid & 31;
    int l = blockIdx.x * 8 + w;
    int nn = l2n[l];
    con[w][lane]      = g_node[cur][(size_t)nn * 32 + lane];
    con[w][32 + lane] = g_link[cur][(size_t)l * 32 + lane];
    con[w][64 + lane] = g_m[(size_t)l * 64 + lane];
    con[w][96 + lane] = g_m[(size_t)l * 64 + 32 + lane];
    __syncthreads();
    float acc = sbe[lane];
    #pragma unroll
    for (int c = 0; c < 128; c++) acc += con[w][c] * sWe[c * 32 + lane];
    g_link[nxt][(size_t)l * 32 + lane] = acc;
    sL[w][lane] = acc;
    __syncwarp();
    int s = senders[l];
    const float* zr = g_z + (size_t)s * 1056;
    float macc = zr[1024 + lane];
    #pragma unroll
    for (int c = 0; c < 32; c++) macc += sL[w][c] * zr[c * 32 + lane];
    atomicAdd(&g_node[nxt][(size_t)recv[l] * 32 + lane], macc);
}

// ---------------- readout: 32 paths/block (4 per warp) --------------------
__global__ void __launch_bounds__(256) readout_kernel(
    const float* __restrict__ rw1, const float* __restrict__ rb1,
    const float* __restrict__ rw2, const float* __restrict__ rb2,
    const float* __restrict__ fw,  const float* __restrict__ fb,
    float* __restrict__ out) {
    __shared__ float sw1[2048], sw2[1024], sfw[96];
    __shared__ float shp[8][64], sr1[8][33];
    int tid = threadIdx.x, w = tid >> 5, lane = tid & 31;
    for (int i = tid; i < 2048; i += 256) sw1[i] = rw1[i];
    for (int i = tid; i < 1024; i += 256) sw2[i] = rw2[i];
    if (tid < 96) sfw[tid] = fw[tid];
    __syncthreads();
    float rb1l = rb1[lane], rb2l = rb2[lane], fb0 = fb[0];
    #pragma unroll
    for (int it = 0; it < 4; it++) {
        int p = blockIdx.x * 32 + w * 4 + it;
        int pcl = (p < NP) ? p : NP - 1;
        shp[w][lane]      = g_path[(size_t)pcl * 64 + lane];
        shp[w][32 + lane] = g_path[(size_t)pcl * 64 + 32 + lane];
        __syncwarp();
        float acc = rb1l;
        #pragma unroll
        for (int i = 0; i < 64; i++) acc += shp[w][i] * sw1[i * 32 + lane];
        float r1 = selu_f(acc);
        sr1[w][lane] = r1;
        __syncwarp();
        float acc2 = rb2l;
        #pragma unroll
        for (int i = 0; i < 32; i++) acc2 += sr1[w][i] * sw2[i * 32 + lane];
        float r2 = selu_f(acc2);
        float part = r2 * sfw[lane] + shp[w][lane] * sfw[32 + lane]
                   + shp[w][32 + lane] * sfw[64 + lane];
        #pragma unroll
        for (int o = 16; o; o >>= 1) part += __shfl_down_sync(0xffffffffu, part, o);
        if (lane == 0 && p < NP) out[p] = part + fb0;
        __syncwarp();
    }
}

// ---------------------------- launcher ------------------------------------
extern "C" void kernel_launch(void* const* d_in, const int* in_sizes, int n_in,
                              void* d_out, int out_size) {
    const float* link_init = (const float*)d_in[0];
    const float* node_init = (const float*)d_in[1];
    const float* path_init = (const float*)d_in[2];
    const float* gru_wx    = (const float*)d_in[3];
    const float* gru_wh    = (const float*)d_in[4];
    const float* gru_b     = (const float*)d_in[5];
    const float* e_w1      = (const float*)d_in[6];
    const float* e_b1      = (const float*)d_in[7];
    const float* e_w2      = (const float*)d_in[8];
    const float* e_b2      = (const float*)d_in[9];
    const float* ecc_wk    = (const float*)d_in[10];
    const float* ecc_bk    = (const float*)d_in[11];
    const float* ecc_wroot = (const float*)d_in[12];
    const float* ecc_broot = (const float*)d_in[13];
    const float* r_w1      = (const float*)d_in[14];
    const float* r_b1      = (const float*)d_in[15];
    const float* r_w2      = (const float*)d_in[16];
    const float* r_b2      = (const float*)d_in[17];
    const float* f_w       = (const float*)d_in[18];
    const float* f_b       = (const float*)d_in[19];
    const int* l2p   = (const int*)d_in[22];
    const int* n2p   = (const int*)d_in[23];
    const int* l2n   = (const int*)d_in[24];
    const int* senders   = (const int*)d_in[25];
    const int* receivers = (const int*)d_in[26];
    float* out = (float*)d_out;

    cudaFuncSetAttribute((const void*)gru_kernel<1, 1>,
                         cudaFuncAttributeMaxDynamicSharedMemorySize, GRU_SMEM_BYTES);
    cudaFuncSetAttribute((const void*)gru_kernel<0, 0>,
                         cudaFuncAttributeMaxDynamicSharedMemorySize, GRU_SMEM_BYTES);

    prep_all_k<<<193, 256>>>(gru_wh, gru_b, e_w1, e_b1, e_w2, e_b2, ecc_wk);   // 0
    init_all_k<<<20625, 256>>>(link_init, node_init, path_init);               // 1
    lxnx1_kernel<<<3125, 192>>>(gru_wx, gru_b, link_init, node_init);          // 2
    gru_kernel<1, 1><<<782, 256, GRU_SMEM_BYTES>>>(l2p, n2p);                  // 3
    z_kernel<<<dim3(313, 2), 256>>>(ecc_bk, 0);                                // 4
    root_kernel<<<625, 256>>>(ecc_wroot, ecc_broot, 0, 1);                     // 5
    edge_msg_kernel<<<2500, 256>>>(l2n, senders, receivers, 0, 1);             // 6
    lxnx_kernel<<<3125, 192>>>(gru_wx, gru_b, 1);                              // 7
    gru_kernel<0, 0><<<782, 256, GRU_SMEM_BYTES>>>(l2p, n2p);                  // 8
    readout_kernel<<<1563, 256>>>(r_w1, r_b1, r_w2, r_b2, f_w, f_b, out);      // 9
}

// round 12
// speedup vs baseline: 1.4120x; 1.0538x over previous
#include <cuda_runtime.h>
#include <math.h>

#define NN 5000
#define NL 20000
#define NP 50000

typedef unsigned long long ull;

// ------------------------- device-global scratch -------------------------
__device__ __align__(16) float g_link[2][NL * 32];
__device__ __align__(16) float g_node[2][NN * 32];
__device__ __align__(16) float g_path[NP * 64];
__device__ __align__(16) float g_m[NL * 64];
__device__ __align__(16) float g_Lx[NL * 192];
__device__ __align__(16) float g_Nx[NN * 192];
__device__ __align__(16) float g_z[(size_t)NN * 1056];
__device__ __align__(16) float g_W2[32768];
__device__ __align__(16) float g_wpack[12288];
__device__ __align__(16) float g_b1pack[192];
__device__ __align__(16) float g_We[4096];
__device__ __align__(16) float g_be[32];

// ------------------------------ helpers ----------------------------------
__device__ __forceinline__ float sigm(float x) {
    return __fdividef(1.0f, 1.0f + __expf(-x));
}
__device__ __forceinline__ float tanh_fast(float x) {
    float ax = fabsf(x);
    float e  = __expf(-2.0f * ax);
    float t  = __fdividef(1.0f - e, 1.0f + e);
    return copysignf(t, x);
}
__device__ __forceinline__ float selu_f(float x) {
    return x > 0.0f ? 1.0507009873554805f * x
                    : 1.7580993408473766f * (__expf(x) - 1.0f);
}
__device__ __forceinline__ void red4(float* a, float x, float y, float z, float w) {
    asm volatile("red.global.add.v4.f32 [%0], {%1,%2,%3,%4};"
                 :: "l"(a), "f"(x), "f"(y), "f"(z), "f"(w) : "memory");
}
__device__ __forceinline__ ull pack2(float a, float b) {
    ull r; asm("mov.b64 %0, {%1,%2};" : "=l"(r) : "f"(a), "f"(b)); return r;
}
__device__ __forceinline__ void ffma2(ull& acc, ull a, ull b) {
    asm("fma.rn.f32x2 %0, %1, %2, %0;" : "+l"(acc) : "l"(a), "l"(b));
}
__device__ __forceinline__ void unpack2(ull v, float& lo, float& hi) {
    asm("mov.b64 {%0,%1}, %2;" : "=f"(lo), "=f"(hi) : "l"(v));
}

// ------------- merged prep: gru pack | fused edge MLP | W2 permute --------
// wpack quad layout: [i][g][jg] -> contiguous 256B per (i,g) warp load
__global__ void prep_all_k(const float* __restrict__ wh, const float* __restrict__ b,
                           const float* __restrict__ w1, const float* __restrict__ b1,
                           const float* __restrict__ w2, const float* __restrict__ b2,
                           const float* __restrict__ wk) {
    int idx = blockIdx.x * 256 + threadIdx.x;
    if (idx < 12288) {
        int k = idx & 3;
        int q = idx >> 2;           // quad index = (i*3 + g)*16 + jg
        int jg = q & 15;
        int g  = (q >> 4) % 3;
        int i  = (q >> 4) / 3;
        g_wpack[idx] = wh[i * 192 + g * 64 + jg * 4 + k];
    } else if (idx < 12480) {
        int r = idx - 12288;
        int k = r & 3;
        int g = (r >> 2) % 3;
        int jg = (r >> 2) / 3;
        g_b1pack[r] = b[192 + g * 64 + jg * 4 + k];
    } else if (idx < 12480 + 4096) {
        int r = idx - 12480;
        int c = r >> 5, j = r & 31;
        float acc = 0.0f;
        #pragma unroll
        for (int k = 0; k < 32; k++) acc += w1[c * 32 + k] * w2[k * 32 + j];
        g_We[r] = acc;
    } else if (idx < 12480 + 4128) {
        int j = idx - 12480 - 4096;
        float acc = b2[j];
        #pragma unroll
        for (int k = 0; k < 32; k++) acc += b1[k] * w2[k * 32 + j];
        g_be[j] = acc;
    } else if (idx < 12480 + 4128 + 32768) {
        int r = idx - 16608;
        int o = r & 31;
        int i = (r >> 5) & 31;
        int c = r >> 10;
        g_W2[i * 1024 + c * 32 + o] = wk[r];
    }
}

// -------------- merged init: link | node | path | zero m ------------------
__global__ void init_all_k(const float* __restrict__ li,
                           const float* __restrict__ ni,
                           const float* __restrict__ pi) {
    int idx = blockIdx.x * 256 + threadIdx.x;   // 5,280,000 total
    if (idx < NL * 32) {
        int l = idx >> 5, c = idx & 31;
        g_link[0][idx] = (c == 0) ? li[l] : 0.0f;
    } else if (idx < NL * 32 + NN * 32) {
        int r = idx - NL * 32;
        int n = r >> 5, c = r & 31;
        g_node[0][r] = (c == 0) ? ni[n] : 0.0f;
    } else if (idx < NL * 32 + NN * 32 + NP * 64) {
        int r = idx - NL * 32 - NN * 32;
        int p = r >> 6, c = r & 63;
        float v = 0.0f;
        if (c == 0) v = pi[p];
        else if (c == 1) v = pi[NP + p];
        g_path[r] = v;
    } else {
        g_m[idx - 4000000] = 0.0f;
    }
}

// ------ iter-1 Lx/Nx fast path (states are rank-1: only col 0 nonzero) ----
__global__ void __launch_bounds__(192) lxnx1_kernel(const float* __restrict__ wx,
                                                    const float* __restrict__ b,
                                                    const float* __restrict__ li,
                                                    const float* __restrict__ ni) {
    int tid = threadIdx.x;
    bool is_link = (blockIdx.x < 2500);
    int base = is_link ? blockIdx.x * 8 : (blockIdx.x - 2500) * 8;
    float wj = is_link ? wx[tid] : wx[6144 + tid];
    float bj = is_link ? b[tid] : 0.0f;
    const float* init = is_link ? li : ni;
    float* dst = is_link ? g_Lx : g_Nx;
    #pragma unroll
    for (int e = 0; e < 8; e++) {
        float v = init[base + e];
        dst[(size_t)(base + e) * 192 + tid] = v * wj + bj;
    }
}

// ---------- full Lx/Nx (iter 2): blocks [0,2500) links, rest nodes --------
__global__ void __launch_bounds__(192) lxnx_kernel(const float* __restrict__ wx,
                                                   const float* __restrict__ b, int cur) {
    __shared__ float swx[6144];
    __shared__ float sst[8][33];
    int tid = threadIdx.x;
    bool is_link = (blockIdx.x < 2500);
    const float* wsrc = is_link ? wx : wx + 6144;
    for (int r = tid; r < 6144; r += 192) swx[r] = wsrc[r];
    const float* st = is_link ? g_link[cur] : g_node[cur];
    int base = is_link ? blockIdx.x * 8 : (blockIdx.x - 2500) * 8;
    for (int r = tid; r < 256; r += 192) {
        int e = r >> 5, c = r & 31;
        sst[e][c] = st[(size_t)(base + e) * 32 + c];
    }
    __syncthreads();
    int j = tid;
    float bj = is_link ? b[j] : 0.0f;
    float* dst = is_link ? g_Lx : g_Nx;
    for (int e = 0; e < 8; e++) {
        float acc = bj;
        #pragma unroll
        for (int i = 0; i < 32; i++) acc += sst[e][i] * swx[i * 192 + j];
        dst[(size_t)(base + e) * 192 + j] = acc;
    }
}

// --------------------------- fused GRU scan ------------------------------
// h stored TRANSPOSED: shh[buf][p*68 + j]  (bank-conflict-free epilogue)
// weights: quad (i*3+g)*16+jg -> contiguous 256B per (i,g) warp access
#define GRU_SMEM_BYTES 84736

#define GRU_I_BODY(i)                                                        \
    {                                                                        \
        float hv0 = shH[hb0 + (i)];                                          \
        float hv1 = shH[hb1 + (i)];                                          \
        float hv2 = shH[hb2 + (i)];                                          \
        float hv3 = shH[hb3 + (i)];                                          \
        ulonglong2 wz = w2m[((i) * 3 + 0) * 16 + jg];                        \
        ulonglong2 wr = w2m[((i) * 3 + 1) * 16 + jg];                        \
        ulonglong2 wh = w2m[((i) * 3 + 2) * 16 + jg];                        \
        ull hp0 = pack2(hv0, hv0);                                           \
        ull hp1 = pack2(hv1, hv1);                                           \
        ull hp2 = pack2(hv2, hv2);                                           \
        ull hp3 = pack2(hv3, hv3);                                           \
        ffma2(a2[0][0], hp0, wz.x); ffma2(a2[0][1], hp0, wz.y);              \
        ffma2(a2[0][2], hp0, wr.x); ffma2(a2[0][3], hp0, wr.y);              \
        ffma2(a2[0][4], hp0, wh.x); ffma2(a2[0][5], hp0, wh.y);              \
        ffma2(a2[1][0], hp1, wz.x); ffma2(a2[1][1], hp1, wz.y);              \
        ffma2(a2[1][2], hp1, wr.x); ffma2(a2[1][3], hp1, wr.y);              \
        ffma2(a2[1][4], hp1, wh.x); ffma2(a2[1][5], hp1, wh.y);              \
        ffma2(a2[2][0], hp2, wz.x); ffma2(a2[2][1], hp2, wz.y);              \
        ffma2(a2[2][2], hp2, wr.x); ffma2(a2[2][3], hp2, wr.y);              \
        ffma2(a2[2][4], hp2, wh.x); ffma2(a2[2][5], hp2, wh.y);              \
        ffma2(a2[3][0], hp3, wz.x); ffma2(a2[3][1], hp3, wz.y);              \
        ffma2(a2[3][2], hp3, wr.x); ffma2(a2[3][3], hp3, wr.y);              \
        ffma2(a2[3][4], hp3, wh.x); ffma2(a2[3][5], hp3, wh.y);              \
    }

template <int SCATTER, int FIRST>
__global__ void __launch_bounds__(256, 2) gru_kernel(const int* __restrict__ l2p,
                                                     const int* __restrict__ n2p) {
    extern __shared__ float sm[];
    float4* wsm = (float4*)sm;               // 3072 quads
    float*  sb1 = sm + 12288;                // 192
    float*  shh = sm + 12480;                // 2 * 4352  ([p][68] layout)

    int tid = threadIdx.x;
    int pg = tid >> 4, jg = tid & 15;
    int pbase = blockIdx.x * 64;

    const float4* wgl = (const float4*)g_wpack;
    #pragma unroll
    for (int r = 0; r < 12; r++) wsm[r * 256 + tid] = wgl[r * 256 + tid];
    if (tid < 192) sb1[tid] = g_b1pack[tid];

    // stage h transposed: shh[p*68 + j]
    const float4* gp4 = (const float4*)g_path;
    #pragma unroll
    for (int r = 0; r < 4; r++) {
        int idx = r * 256 + tid;
        int p = idx >> 4, iq = idx & 15;
        int pglob = pbase + p; if (pglob >= NP) pglob = NP - 1;
        float4 v = gp4[(size_t)pglob * 16 + iq];
        *(float4*)(shh + p * 68 + iq * 4) = v;
    }
    __syncthreads();

    const ulonglong2* sb2 = (const ulonglong2*)sb1;
    ulonglong2 bA = sb2[jg * 3 + 0];
    ulonglong2 bB = sb2[jg * 3 + 1];
    ulonglong2 bC = sb2[jg * 3 + 2];

    int pid[4]; bool pv[4];
    #pragma unroll
    for (int pp = 0; pp < 4; pp++) {
        int pglob = pbase + pg * 4 + pp;
        pv[pp] = (pglob < NP);
        pid[pp] = pv[pp] ? pglob : NP - 1;
    }
    const int hb0 = (pg * 4 + 0) * 68;
    const int hb1 = (pg * 4 + 1) * 68;
    const int hb2 = (pg * 4 + 2) * 68;
    const int hb3 = (pg * 4 + 3) * 68;

    const float4* Lx4 = (const float4*)g_Lx;
    const float4* Nx4 = (const float4*)g_Nx;
    const ulonglong2* w2m = (const ulonglong2*)wsm;

    int hbuf = 0;
    for (int t = 0; t < 8; t++) {
        float4 gz[4], gr[4], gc[4];
        int liA[4];
        #pragma unroll
        for (int pp = 0; pp < 4; pp++) {
            int e = pid[pp] * 8 + t;
            int li = l2p[e], ni = n2p[e];
            liA[pp] = li;
            const float4* lq = Lx4 + (size_t)li * 48 + jg;
            const float4* nq = Nx4 + (size_t)ni * 48 + jg;
            float4 a0 = lq[0],  b0 = nq[0];
            float4 a1 = lq[16], b1 = nq[16];
            float4 a2q = lq[32], b2q = nq[32];
            gz[pp] = make_float4(a0.x + b0.x, a0.y + b0.y, a0.z + b0.z, a0.w + b0.w);
            gr[pp] = make_float4(a1.x + b1.x, a1.y + b1.y, a1.z + b1.z, a1.w + b1.w);
            gc[pp] = make_float4(a2q.x + b2q.x, a2q.y + b2q.y, a2q.z + b2q.z, a2q.w + b2q.w);
        }

        float* shH  = shh + hbuf * 4352;
        float* shHn = shh + (hbuf ^ 1) * 4352;

        ull a2[4][6];
        #pragma unroll
        for (int pp = 0; pp < 4; pp++) {
            a2[pp][0] = bA.x; a2[pp][1] = bA.y;
            a2[pp][2] = bB.x; a2[pp][3] = bB.y;
            a2[pp][4] = bC.x; a2[pp][5] = bC.y;
        }

        if (FIRST && t == 0) {
            // h0 has only hidden dims 0,1 nonzero — 2-term inner loop (bit-exact)
            GRU_I_BODY(0);
            GRU_I_BODY(1);
        } else {
            #pragma unroll 8
            for (int i = 0; i < 64; i++) GRU_I_BODY(i);
        }

        int j0 = jg * 4;
        #pragma unroll
        for (int pp = 0; pp < 4; pp++) {
            int p = pg * 4 + pp;
            float az0, az1, az2, az3, ar0, ar1, ar2, ar3, ah0, ah1, ah2, ah3;
            unpack2(a2[pp][0], az0, az1); unpack2(a2[pp][1], az2, az3);
            unpack2(a2[pp][2], ar0, ar1); unpack2(a2[pp][3], ar2, ar3);
            unpack2(a2[pp][4], ah0, ah1); unpack2(a2[pp][5], ah2, ah3);
            float z0 = sigm(gz[pp].x + az0);
            float z1 = sigm(gz[pp].y + az1);
            float z2 = sigm(gz[pp].z + az2);
            float z3 = sigm(gz[pp].w + az3);
            float r0 = sigm(gr[pp].x + ar0);
            float r1 = sigm(gr[pp].y + ar1);
            float r2 = sigm(gr[pp].z + ar2);
            float r3 = sigm(gr[pp].w + ar3);
            float c0 = tanh_fast(gc[pp].x + r0 * ah0);
            float c1 = tanh_fast(gc[pp].y + r1 * ah1);
            float c2 = tanh_fast(gc[pp].z + r2 * ah2);
            float c3 = tanh_fast(gc[pp].w + r3 * ah3);
            float4 hold = *(const float4*)(shH + p * 68 + j0);
            float n0 = z0 * hold.x + (1.0f - z0) * c0;
            float n1 = z1 * hold.y + (1.0f - z1) * c1;
            float n2 = z2 * hold.z + (1.0f - z2) * c2;
            float n3 = z3 * hold.w + (1.0f - z3) * c3;
            *(float4*)(shHn + p * 68 + j0) = make_float4(n0, n1, n2, n3);
            if (SCATTER && pv[pp]) {
                red4(g_m + (size_t)liA[pp] * 64 + j0, n0, n1, n2, n3);
            }
        }
        hbuf ^= 1;
        __syncthreads();
    }

    float* shF = shh + hbuf * 4352;
    #pragma unroll
    for (int r = 0; r < 4; r++) {
        int idx = r * 256 + tid;
        int p = idx >> 4, iq = idx & 15;
        int pglob = pbase + p;
        if (pglob < NP) {
            float4 v = *(const float4*)(shF + p * 68 + iq * 4);
            ((float4*)g_path)[(size_t)pglob * 16 + iq] = v;
        }
    }
}

// ------- z[s][c*32+o] = sum_i node[s][i] * W2[i][c*32+o];  + beta cols ----
__global__ void __launch_bounds__(256) z_kernel(const float* __restrict__ bk, int cur) {
    __shared__ __align__(16) float Ns[512];
    int tid = threadIdx.x;
    int n0 = blockIdx.x * 16;
    const float* nst = g_node[cur];
    for (int r = tid; r < 512; r += 256) {
        int i = r >> 4, nl = r & 15;
        int nn = n0 + nl; if (nn >= NN) nn = NN - 1;
        Ns[r] = nst[(size_t)nn * 32 + i];
    }
    __syncthreads();
    int o = blockIdx.y * 512 + tid;
    ull acc0[8], acc1[8];
    #pragma unroll
    for (int q = 0; q < 8; q++) { acc0[q] = 0ull; acc1[q] = 0ull; }
    for (int i = 0; i < 32; i++) {
        float w0 = g_W2[i * 1024 + o];
        float w1 = g_W2[i * 1024 + o + 256];
        ull w0p = pack2(w0, w0);
        ull w1p = pack2(w1, w1);
        const ulonglong2* np = (const ulonglong2*)(Ns + i * 16);
        #pragma unroll
        for (int q2 = 0; q2 < 4; q2++) {
            ulonglong2 nv = np[q2];
            ffma2(acc0[q2 * 2 + 0], nv.x, w0p);
            ffma2(acc0[q2 * 2 + 1], nv.y, w0p);
            ffma2(acc1[q2 * 2 + 0], nv.x, w1p);
            ffma2(acc1[q2 * 2 + 1], nv.y, w1p);
        }
    }
    #pragma unroll
    for (int q = 0; q < 8; q++) {
        float v0, v1, u0, u1;
        unpack2(acc0[q], v0, v1);
        unpack2(acc1[q], u0, u1);
        int na = n0 + 2 * q, nb = n0 + 2 * q + 1;
        if (na < NN) { g_z[(size_t)na * 1056 + o] = v0; g_z[(size_t)na * 1056 + o + 256] = u0; }
        if (nb < NN) { g_z[(size_t)nb * 1056 + o] = v1; g_z[(size_t)nb * 1056 + o + 256] = u1; }
    }
    if (blockIdx.y == 0) {
        int nl = tid >> 5;
        int oo = tid & 31;
        float b0 = 0.0f, b1 = 0.0f;
        #pragma unroll
        for (int i = 0; i < 32; i++) {
            float bkv = bk[i * 32 + oo];
            b0 += Ns[i * 16 + nl] * bkv;
            b1 += Ns[i * 16 + nl + 8] * bkv;
        }
        if (n0 + nl < NN)     g_z[(size_t)(n0 + nl) * 1056 + 1024 + oo] = b0;
        if (n0 + nl + 8 < NN) g_z[(size_t)(n0 + nl + 8) * 1056 + 1024 + oo] = b1;
    }
}

// --------- root (stores): node1 = broot + node0@wroot ---------------------
__global__ void __launch_bounds__(256) root_kernel(const float* __restrict__ wroot,
                                                   const float* __restrict__ broot,
                                                   int cur, int nxt) {
    __shared__ float sw[1024];
    int tid = threadIdx.x;
    for (int i = tid; i < 1024; i += 256) sw[i] = wroot[i];
    __syncthreads();
    int w = tid >> 5, lane = tid & 31;
    int n = blockIdx.x * 8 + w;
    const float* nr = g_node[cur] + (size_t)n * 32;
    float acc = broot[lane];
    #pragma unroll
    for (int i = 0; i < 32; i++) acc += nr[i] * sw[i * 32 + lane];
    g_node[nxt][(size_t)n * 32 + lane] = acc;
}

// ----- fused edge MLP + ECC message --------------------------------------
__global__ void __launch_bounds__(256) edge_msg_kernel(const int* __restrict__ l2n,
                                                       const int* __restrict__ senders,
                                                       const int* __restrict__ recv,
                                                       int cur, int nxt) {
    __shared__ float sWe[4096];
    __shared__ float sbe[32];
    __shared__ float con[8][128];
    __shared__ float sL[8][32];
    int tid = threadIdx.x;
    for (int i = tid; i < 4096; i += 256) sWe[i] = g_We[i];
    if (tid < 32) sbe[tid] = g_be[tid];
    int w = tid >> 5, lane = tid & 31;
    int l = blockIdx.x * 8 + w;
    int nn = l2n[l];
    con[w][lane]      = g_node[cur][(size_t)nn * 32 + lane];
    con[w][32 + lane] = g_link[cur][(size_t)l * 32 + lane];
    con[w][64 + lane] = g_m[(size_t)l * 64 + lane];
    con[w][96 + lane] = g_m[(size_t)l * 64 + 32 + lane];
    __syncthreads();
    float acc = sbe[lane];
    #pragma unroll
    for (int c = 0; c < 128; c++) acc += con[w][c] * sWe[c * 32 + lane];
    g_link[nxt][(size_t)l * 32 + lane] = acc;
    sL[w][lane] = acc;
    __syncwarp();
    int s = senders[l];
    const float* zr = g_z + (size_t)s * 1056;
    float macc = zr[1024 + lane];
    #pragma unroll
    for (int c = 0; c < 32; c++) macc += sL[w][c] * zr[c * 32 + lane];
    atomicAdd(&g_node[nxt][(size_t)recv[l] * 32 + lane], macc);
}

// ---------------- readout: 32 paths/block (4 per warp) --------------------
__global__ void __launch_bounds__(256) readout_kernel(
    const float* __restrict__ rw1, const float* __restrict__ rb1,
    const float* __restrict__ rw2, const float* __restrict__ rb2,
    const float* __restrict__ fw,  const float* __restrict__ fb,
    float* __restrict__ out) {
    __shared__ float sw1[2048], sw2[1024], sfw[96];
    __shared__ float shp[8][64], sr1[8][33];
    int tid = threadIdx.x, w = tid >> 5, lane = tid & 31;
    for (int i = tid; i < 2048; i += 256) sw1[i] = rw1[i];
    for (int i = tid; i < 1024; i += 256) sw2[i] = rw2[i];
    if (tid < 96) sfw[tid] = fw[tid];
    __syncthreads();
    float rb1l = rb1[lane], rb2l = rb2[lane], fb0 = fb[0];
    #pragma unroll
    for (int it = 0; it < 4; it++) {
        int p = blockIdx.x * 32 + w * 4 + it;
        int pcl = (p < NP) ? p : NP - 1;
        shp[w][lane]      = g_path[(size_t)pcl * 64 + lane];
        shp[w][32 + lane] = g_path[(size_t)pcl * 64 + 32 + lane];
        __syncwarp();
        float acc = rb1l;
        #pragma unroll
        for (int i = 0; i < 64; i++) acc += shp[w][i] * sw1[i * 32 + lane];
        float r1 = selu_f(acc);
        sr1[w][lane] = r1;
        __syncwarp();
        float acc2 = rb2l;
        #pragma unroll
        for (int i = 0; i < 32; i++) acc2 += sr1[w][i] * sw2[i * 32 + lane];
        float r2 = selu_f(acc2);
        float part = r2 * sfw[lane] + shp[w][lane] * sfw[32 + lane]
                   + shp[w][32 + lane] * sfw[64 + lane];
        #pragma unroll
        for (int o = 16; o; o >>= 1) part += __shfl_down_sync(0xffffffffu, part, o);
        if (lane == 0 && p < NP) out[p] = part + fb0;
        __syncwarp();
    }
}

// ---------------------------- launcher ------------------------------------
extern "C" void kernel_launch(void* const* d_in, const int* in_sizes, int n_in,
                              void* d_out, int out_size) {
    const float* link_init = (const float*)d_in[0];
    const float* node_init = (const float*)d_in[1];
    const float* path_init = (const float*)d_in[2];
    const float* gru_wx    = (const float*)d_in[3];
    const float* gru_wh    = (const float*)d_in[4];
    const float* gru_b     = (const float*)d_in[5];
    const float* e_w1      = (const float*)d_in[6];
    const float* e_b1      = (const float*)d_in[7];
    const float* e_w2      = (const float*)d_in[8];
    const float* e_b2      = (const float*)d_in[9];
    const float* ecc_wk    = (const float*)d_in[10];
    const float* ecc_bk    = (const float*)d_in[11];
    const float* ecc_wroot = (const float*)d_in[12];
    const float* ecc_broot = (const float*)d_in[13];
    const float* r_w1      = (const float*)d_in[14];
    const float* r_b1      = (const float*)d_in[15];
    const float* r_w2      = (const float*)d_in[16];
    const float* r_b2      = (const float*)d_in[17];
    const float* f_w       = (const float*)d_in[18];
    const float* f_b       = (const float*)d_in[19];
    const int* l2p   = (const int*)d_in[22];
    const int* n2p   = (const int*)d_in[23];
    const int* l2n   = (const int*)d_in[24];
    const int* senders   = (const int*)d_in[25];
    const int* receivers = (const int*)d_in[26];
    float* out = (float*)d_out;

    cudaFuncSetAttribute((const void*)gru_kernel<1, 1>,
                         cudaFuncAttributeMaxDynamicSharedMemorySize, GRU_SMEM_BYTES);
    cudaFuncSetAttribute((const void*)gru_kernel<0, 0>,
                         cudaFuncAttributeMaxDynamicSharedMemorySize, GRU_SMEM_BYTES);

    prep_all_k<<<193, 256>>>(gru_wh, gru_b, e_w1, e_b1, e_w2, e_b2, ecc_wk);   // 0
    init_all_k<<<20625, 256>>>(link_init, node_init, path_init);               // 1
    lxnx1_kernel<<<3125, 192>>>(gru_wx, gru_b, link_init, node_init);          // 2
    gru_kernel<1, 1><<<782, 256, GRU_SMEM_BYTES>>>(l2p, n2p);                  // 3
    z_kernel<<<dim3(313, 2), 256>>>(ecc_bk, 0);                                // 4
    root_kernel<<<625, 256>>>(ecc_wroot, ecc_broot, 0, 1);                     // 5
    edge_msg_kernel<<<2500, 256>>>(l2n, senders, receivers, 0, 1);             // 6
    lxnx_kernel<<<3125, 192>>>(gru_wx, gru_b, 1);                              // 7
    gru_kernel<0, 0><<<782, 256, GRU_SMEM_BYTES>>>(l2p, n2p);                  // 8
    readout_kernel<<<1563, 256>>>(r_w1, r_b1, r_w2, r_b2, f_w, f_b, out);      // 9
}